// round 1
// baseline (speedup 1.0000x reference)
#include <cuda_runtime.h>
#include <math.h>

#define NB 2
#define NH 16
#define SL 1024
#define HD 64
#define NBH 32
#define NS 4
#define LMAXC 2048
#define PLANE (NBH * SL * HD)   // 2,097,152 floats per (real/imag) plane

// Scratch (static device globals: allocation-free at launch time)
__device__ float g_M[(size_t)NBH * SL * SL];   // |C|/sqrt(D), 128 MB
__device__ float g_a[NS * SL];                 // scale magnitude tables
__device__ float g_mx[NBH * NS * SL];          // per-row softmax max
__device__ float g_iZ[NBH * NS * SL];          // per-row 1/sumexp
__device__ float g_sc[SL];                     // expert sum-cos per l
__device__ float g_ss[SL];                     // expert sum-sin per l

// ---------------------------------------------------------------------------
// Fast exp on the FMA pipe (avoids MUFU EX2 throughput wall).
// Valid for the benign range here (args in [-~0.1, 0]); rel err < 3e-6.
// ---------------------------------------------------------------------------
__device__ __forceinline__ float fast_exp(float x) {
    float y = x * 1.4426950408889634f;          // log2(e)
    float t = y + 12582912.0f;                  // round-to-nearest via magic
    int   ni = __float_as_int(t) - 0x4B400000;  // integer part
    float n = t - 12582912.0f;
    float r = y - n;                            // r in [-0.5, 0.5]
    float p = 0.0013333558f;                    // 2^r Taylor (deg 5)
    p = fmaf(p, r, 0.0096181291f);
    p = fmaf(p, r, 0.0555041087f);
    p = fmaf(p, r, 0.2402265069f);
    p = fmaf(p, r, 0.6931471806f);
    p = fmaf(p, r, 1.0f);
    return __int_as_float(__float_as_int(p) + (ni << 23));
}

// ---------------------------------------------------------------------------
// Kernel A: tiny precompute of a_s[l], expert Sc/Ss[l]
// |p(t)|^2 = 3 + 2cos(t) + 2cos(t/2) + 2cos(3t/2); norm over full LMAX=2048.
// ---------------------------------------------------------------------------
__device__ __forceinline__ float pmag2(float t) {
    return 3.f + 2.f * cosf(t) + 2.f * cosf(0.5f * t) + 2.f * cosf(1.5f * t);
}

__global__ void k_tables() {
    __shared__ float red[1024];
    int l = threadIdx.x;
    const float freqs[NS] = {1.f, 0.5f, 0.25f, 0.1f};
    for (int s = 0; s < NS; s++) {
        float step = 6.283185307179586f * freqs[s] / (float)(LMAXC - 1);
        float p0 = pmag2((float)l * step);
        float p1 = pmag2((float)(l + 1024) * step);
        red[l] = p0 + p1;
        __syncthreads();
        for (int o = 512; o > 0; o >>= 1) {
            if (l < o) red[l] += red[l + o];
            __syncthreads();
        }
        float inv = rsqrtf(red[0]);
        __syncthreads();
        g_a[s * SL + l] = sqrtf(fmaxf(p0, 0.f)) * inv;
    }
    // Expert per-l frequency sums: freqs (0.3+0.1i, 0.2+0.1i, 0.1+0.1i), i=0..7
    float t = (float)l * (6.283185307179586f / (float)(LMAXC - 1));
    float sc = 0.f, ss = 0.f;
    #pragma unroll
    for (int i = 0; i < 8; i++) {
        float fb = 0.1f * (float)i;
        sc += cosf((0.3f + fb) * t) + cosf((0.2f + fb) * t) + cosf((0.1f + fb) * t);
        ss += sinf((0.3f + fb) * t) + sinf((0.2f + fb) * t) + sinf((0.1f + fb) * t);
    }
    g_sc[l] = sc;
    g_ss[l] = ss;
}

// ---------------------------------------------------------------------------
// Kernel B: M[bh,l,m] = |sum_d Qc[l,d]*Kc[m,d]| / sqrt(D)    (complex, no conj)
// Tiled 64x64 output per block, K-dim (=D=64) processed in two 32-wide slabs.
// ---------------------------------------------------------------------------
__global__ void k_scores(const float* __restrict__ Qr, const float* __restrict__ Qi,
                         const float* __restrict__ Kr, const float* __restrict__ Ki) {
    __shared__ float sQr[64][33], sQi[64][33], sKr[64][33], sKi[64][33];
    int bh = blockIdx.z;
    int l0 = blockIdx.y * 64;
    int m0 = blockIdx.x * 64;
    int tx = threadIdx.x, ty = threadIdx.y;
    int tid = ty * 16 + tx;

    const float* qr = Qr + (size_t)(bh * SL + l0) * HD;
    const float* qi = Qi + (size_t)(bh * SL + l0) * HD;
    const float* kr = Kr + (size_t)(bh * SL + m0) * HD;
    const float* ki = Ki + (size_t)(bh * SL + m0) * HD;

    float ar[4][4] = {}, ai[4][4] = {};

    for (int kk = 0; kk < HD; kk += 32) {
        for (int e = tid; e < 64 * 32; e += 256) {
            int row = e >> 5, col = e & 31;
            sQr[row][col] = qr[row * HD + kk + col];
            sQi[row][col] = qi[row * HD + kk + col];
            sKr[row][col] = kr[row * HD + kk + col];
            sKi[row][col] = ki[row * HD + kk + col];
        }
        __syncthreads();
        #pragma unroll 8
        for (int k = 0; k < 32; k++) {
            float qrv[4], qiv[4], krv[4], kiv[4];
            #pragma unroll
            for (int i = 0; i < 4; i++) { qrv[i] = sQr[ty * 4 + i][k]; qiv[i] = sQi[ty * 4 + i][k]; }
            #pragma unroll
            for (int j = 0; j < 4; j++) { krv[j] = sKr[tx * 4 + j][k]; kiv[j] = sKi[tx * 4 + j][k]; }
            #pragma unroll
            for (int i = 0; i < 4; i++)
                #pragma unroll
                for (int j = 0; j < 4; j++) {
                    ar[i][j] = fmaf(qrv[i], krv[j], ar[i][j]);
                    ar[i][j] = fmaf(-qiv[i], kiv[j], ar[i][j]);
                    ai[i][j] = fmaf(qrv[i], kiv[j], ai[i][j]);
                    ai[i][j] = fmaf(qiv[i], krv[j], ai[i][j]);
                }
        }
        __syncthreads();
    }

    #pragma unroll
    for (int i = 0; i < 4; i++) {
        int l = l0 + ty * 4 + i;
        float4 o;
        float* po = &o.x;
        #pragma unroll
        for (int j = 0; j < 4; j++) {
            float cr = ar[i][j], ci = ai[i][j];
            po[j] = sqrtf(fmaf(cr, cr, ci * ci)) * 0.125f;   // /sqrt(64)
        }
        *(float4*)&g_M[((size_t)(bh * SL + l)) * SL + m0 + tx * 4] = o;
    }
}

// ---------------------------------------------------------------------------
// Kernel C1: per-row, per-scale softmax stats (max, 1/sumexp).
// mag_s[l,m] = a_s[l] * a_s[m] * M[l,m]. One warp per row; 8 rows per block.
// ---------------------------------------------------------------------------
__global__ void k_stats() {
    __shared__ float sa[NS * SL];   // 16 KB scale tables
    int tid = threadIdx.x;
    for (int e = tid; e < NS * SL; e += 256) sa[e] = g_a[e];
    __syncthreads();

    int warp = tid >> 5, lane = tid & 31;
    int l = blockIdx.x * 8 + warp;
    int bh = blockIdx.y;
    const float* Mrow = g_M + ((size_t)(bh * SL + l)) * SL;

    float cl[NS], mx[NS] = {0.f, 0.f, 0.f, 0.f};
    #pragma unroll
    for (int s = 0; s < NS; s++) cl[s] = sa[s * SL + l];

    for (int m = lane; m < SL; m += 32) {
        float v = Mrow[m];
        #pragma unroll
        for (int s = 0; s < NS; s++) mx[s] = fmaxf(mx[s], sa[s * SL + m] * v);
    }
    #pragma unroll
    for (int o = 16; o > 0; o >>= 1)
        #pragma unroll
        for (int s = 0; s < NS; s++)
            mx[s] = fmaxf(mx[s], __shfl_xor_sync(0xffffffffu, mx[s], o));

    float fmx[NS], sum[NS] = {0.f, 0.f, 0.f, 0.f};
    #pragma unroll
    for (int s = 0; s < NS; s++) fmx[s] = cl[s] * mx[s];

    for (int m = lane; m < SL; m += 32) {
        float v = Mrow[m];   // L1 hit (second pass over same 4 KB row)
        #pragma unroll
        for (int s = 0; s < NS; s++) {
            float t = sa[s * SL + m] * v;
            sum[s] += fast_exp(fmaf(cl[s], t, -fmx[s]));
        }
    }
    #pragma unroll
    for (int o = 16; o > 0; o >>= 1)
        #pragma unroll
        for (int s = 0; s < NS; s++)
            sum[s] += __shfl_xor_sync(0xffffffffu, sum[s], o);

    if (lane == 0) {
        #pragma unroll
        for (int s = 0; s < NS; s++) {
            g_mx[(bh * NS + s) * SL + l] = fmx[s];
            g_iZ[(bh * NS + s) * SL + l] = 1.0f / sum[s];
        }
    }
}

// ---------------------------------------------------------------------------
// Kernel C2: O = (sum_s w_s) @ [Vr|Vi] with W computed on the fly, then
// fused *0.5 and expert complex multiply epilogue.
// Block: 64 query rows; keys in 32-wide tiles; Vcat interleaved (r,i) pairs.
// ---------------------------------------------------------------------------
__global__ void k_av(const float* __restrict__ Vr, const float* __restrict__ Vi,
                     float* __restrict__ out) {
    __shared__ float Ws[64 * 32];        // W tile [row][k]      8 KB
    __shared__ float Vc[32 * 128];       // Vcat [k][2d|2d+1]   16 KB
    __shared__ float am[NS * 32];        // a_s[m] for tile
    __shared__ float rcl[NS * 64], rmx[NS * 64], riz[NS * 64];

    int bh = blockIdx.y;
    int l0 = blockIdx.x * 64;
    int tx = threadIdx.x, ty = threadIdx.y;
    int tid = ty * 16 + tx;

    for (int e = tid; e < NS * 64; e += 256) {
        int s = e >> 6, r = e & 63;
        rcl[e] = g_a[s * SL + l0 + r];
        rmx[e] = g_mx[(bh * NS + s) * SL + l0 + r];
        riz[e] = g_iZ[(bh * NS + s) * SL + l0 + r];
    }

    float acc[4][8] = {};
    const float* vr = Vr + (size_t)bh * SL * HD;
    const float* vi = Vi + (size_t)bh * SL * HD;

    for (int m0 = 0; m0 < SL; m0 += 32) {
        __syncthreads();  // protect prev GEMM reads (and initial rcl load)
        if (tid < NS * 32) {
            int s = tid >> 5, j = tid & 31;
            am[tid] = g_a[s * SL + m0 + j];
        }
        for (int e = tid; e < 32 * 64; e += 256) {
            int k = e >> 6, d = e & 63;
            Vc[k * 128 + 2 * d]     = vr[(m0 + k) * HD + d];
            Vc[k * 128 + 2 * d + 1] = vi[(m0 + k) * HD + d];
        }
        __syncthreads();
        for (int e = tid; e < 64 * 32; e += 256) {
            int r = e >> 5, j = e & 31;
            float v = g_M[((size_t)(bh * SL + l0 + r)) * SL + m0 + j];
            float w = 0.f;
            #pragma unroll
            for (int s = 0; s < NS; s++) {
                float t = am[s * 32 + j] * v;
                w = fmaf(fast_exp(fmaf(rcl[s * 64 + r], t, -rmx[s * 64 + r])),
                         riz[s * 64 + r], w);
            }
            Ws[r * 32 + j] = w;
        }
        __syncthreads();
        #pragma unroll 4
        for (int k = 0; k < 32; k++) {
            float4 v0 = *(const float4*)&Vc[k * 128 + tx * 8];
            float4 v1 = *(const float4*)&Vc[k * 128 + tx * 8 + 4];
            #pragma unroll
            for (int i = 0; i < 4; i++) {
                float w = Ws[(ty * 4 + i) * 32 + k];
                acc[i][0] = fmaf(w, v0.x, acc[i][0]);
                acc[i][1] = fmaf(w, v0.y, acc[i][1]);
                acc[i][2] = fmaf(w, v0.z, acc[i][2]);
                acc[i][3] = fmaf(w, v0.w, acc[i][3]);
                acc[i][4] = fmaf(w, v1.x, acc[i][4]);
                acc[i][5] = fmaf(w, v1.y, acc[i][5]);
                acc[i][6] = fmaf(w, v1.z, acc[i][6]);
                acc[i][7] = fmaf(w, v1.w, acc[i][7]);
            }
        }
    }

    // Epilogue: *0.5 (scale avg) and expert complex multiply, fused constant:
    // KC = 0.5 / (sqrt(LMAX) * sqrt(24)) = 0.5 / sqrt(49152)
    const float KC = 0.00225527461f;
    float cph[4], sph[4];
    #pragma unroll
    for (int p = 0; p < 4; p++) {
        int d = tx * 4 + p;
        float ang = 6.283185307179586f * (float)d / 64.f;
        sph[p] = sinf(ang);
        cph[p] = cosf(ang);
    }
    #pragma unroll
    for (int i = 0; i < 4; i++) {
        int l = l0 + ty * 4 + i;
        float scl = g_sc[l], ssl = g_ss[l];
        float4 o_r, o_i;
        float* pr = &o_r.x;
        float* pi = &o_i.x;
        #pragma unroll
        for (int p = 0; p < 4; p++) {
            float orr = acc[i][2 * p];
            float oii = acc[i][2 * p + 1];
            float epr = KC * (cph[p] * scl - sph[p] * ssl);
            float epi = KC * (sph[p] * scl + cph[p] * ssl);
            pr[p] = orr * epr - oii * epi;
            pi[p] = orr * epi + oii * epr;
        }
        size_t base = ((size_t)(bh * SL + l)) * HD + tx * 4;
        *(float4*)&out[base]         = o_r;
        *(float4*)&out[base + PLANE] = o_i;
    }
}

// ---------------------------------------------------------------------------
extern "C" void kernel_launch(void* const* d_in, const int* in_sizes, int n_in,
                              void* d_out, int out_size) {
    const float* Qr = (const float*)d_in[0];
    const float* Qi = (const float*)d_in[1];
    const float* Kr = (const float*)d_in[2];
    const float* Ki = (const float*)d_in[3];
    const float* Vr = (const float*)d_in[4];
    const float* Vi = (const float*)d_in[5];
    float* out = (float*)d_out;

    k_tables<<<1, 1024>>>();
    k_scores<<<dim3(16, 16, 32), dim3(16, 16)>>>(Qr, Qi, Kr, Ki);
    k_stats<<<dim3(128, 32), 256>>>();
    k_av<<<dim3(16, 32), dim3(16, 16)>>>(Vr, Vi, out);
}